// round 1
// baseline (speedup 1.0000x reference)
#include <cuda_runtime.h>
#include <cstdint>
#include <math.h>

#define Bn 32
#define Qn 300
#define Cn 81
#define Pn 300
#define An 29

// Output layout (flattened float32, concatenated in reference return order)
#define LEN_SCORES ((size_t)Bn * Qn)                        // 9600
#define LEN_LABELS ((size_t)Bn * Qn)                        // 9600
#define LEN_BOXES  ((size_t)Bn * Qn * 4)                    // 38400
#define LEN_SCORE  ((size_t)Bn * An * Qn * (Qn + 1))        // 83,798,400
#define LEN_HMASK  ((size_t)Bn * Qn)                        // 9600
#define LEN_OMASK  ((size_t)Bn * (Qn + 1))                  // 9632

#define OFF_SCORES ((size_t)0)
#define OFF_LABELS (OFF_SCORES + LEN_SCORES)
#define OFF_BOXES  (OFF_LABELS + LEN_LABELS)
#define OFF_SCORE  (OFF_BOXES  + LEN_BOXES)
#define OFF_HMASK  (OFF_SCORE  + LEN_SCORE)
#define OFF_OMASK  (OFF_HMASK  + LEN_HMASK)

// ---------------------------------------------------------------------------
// Kernel 1: per-(b,q) softmax stats + boxes + masks. One warp per row.
// ---------------------------------------------------------------------------
__global__ void postproc_rows_kernel(const float* __restrict__ logits,
                                     const float* __restrict__ boxes_in,
                                     const float* __restrict__ tsizes,
                                     float* __restrict__ out) {
    int gwarp = (blockIdx.x * blockDim.x + threadIdx.x) >> 5;
    int lane  = threadIdx.x & 31;
    if (gwarp >= Bn * Qn) return;
    int b = gwarp / Qn;
    int q = gwarp % Qn;

    const float* row = logits + (size_t)gwarp * Cn;

    // Load up to 3 classes per lane (81 = 32 + 32 + 17)
    float v0 = (lane      < Cn) ? row[lane]      : -INFINITY;
    float v1 = (lane + 32 < Cn) ? row[lane + 32] : -INFINITY;
    float v2 = (lane + 64 < Cn) ? row[lane + 64] : -INFINITY;

    // Max over all C classes (for softmax stability)
    float m_all = fmaxf(v0, fmaxf(v1, v2));
    #pragma unroll
    for (int off = 16; off > 0; off >>= 1)
        m_all = fmaxf(m_all, __shfl_xor_sync(0xffffffffu, m_all, off));

    // Argmax over first C-1 = 80 classes (first-index-wins on ties)
    float bv = -INFINITY; int bi = 0;
    if (lane < Cn - 1)            { bv = v0; bi = lane; }
    if (lane + 32 < Cn - 1 && v1 > bv) { bv = v1; bi = lane + 32; }
    if (lane + 64 < Cn - 1 && v2 > bv) { bv = v2; bi = lane + 64; }
    #pragma unroll
    for (int off = 16; off > 0; off >>= 1) {
        float ov = __shfl_xor_sync(0xffffffffu, bv, off);
        int   oi = __shfl_xor_sync(0xffffffffu, bi, off);
        if (ov > bv || (ov == bv && oi < bi)) { bv = ov; bi = oi; }
    }

    // Sum of exp
    float s = 0.f;
    if (lane      < Cn) s += expf(v0 - m_all);
    if (lane + 32 < Cn) s += expf(v1 - m_all);
    if (lane + 64 < Cn) s += expf(v2 - m_all);
    #pragma unroll
    for (int off = 16; off > 0; off >>= 1)
        s += __shfl_xor_sync(0xffffffffu, s, off);

    float score = expf(bv - m_all) / s;

    if (lane == 0) {
        out[OFF_SCORES + gwarp] = score;
        out[OFF_LABELS + gwarp] = (float)bi;
        out[OFF_HMASK  + gwarp] = (bi == 1 && score > 0.f) ? 1.f : 0.f;
        out[OFF_OMASK + (size_t)b * (Qn + 1) + q] = (score > 0.f) ? 1.f : 0.f;
        if (q == 0)
            out[OFF_OMASK + (size_t)b * (Qn + 1) + Qn] = 1.f;
    }

    // Boxes: cxcywh -> xyxy, scaled by [w,h,w,h]
    if (lane < 4) {
        float cxy = boxes_in[(size_t)gwarp * 4 + (lane & 1)];        // cx or cy
        float wh  = boxes_in[(size_t)gwarp * 4 + 2 + (lane & 1)];    // w or h
        float v   = cxy + ((lane < 2) ? -0.5f : 0.5f) * wh;
        float img_h = tsizes[b * 2 + 0];
        float img_w = tsizes[b * 2 + 1];
        float scale = (lane & 1) ? img_h : img_w;
        out[OFF_BOXES + (size_t)gwarp * 4 + lane] = v * scale;
    }
}

// ---------------------------------------------------------------------------
// Kernel 2: scatter sigmoid(pred_actions) into score[b, a, h, o].
// One block (32 threads) per batch; serial over p so duplicate (h,o) pairs
// resolve last-wins in p-order (matching sequential scatter-set semantics).
// Runtime-detects whether pairs are int32 or int64 (JAX x64 ambiguity).
// ---------------------------------------------------------------------------
__global__ void scatter_actions_kernel(const float* __restrict__ actions,
                                       const void*  __restrict__ pairs_raw,
                                       float* __restrict__ out) {
    int b = blockIdx.x;
    int lane = threadIdx.x;  // blockDim.x == 32

    // dtype detection: if data is int64 (values < Q, nonneg), every odd 32-bit
    // word is the zero high-half. Sample 32 odd words.
    const int* pw = (const int*)pairs_raw;
    int nonzero = (pw[2 * lane + 1] != 0) ? 1 : 0;
    unsigned mask = __ballot_sync(0xffffffffu, nonzero);
    bool is64 = (mask == 0u);

    const float* act_b = actions + (size_t)b * Pn * An;
    float* score_base = out + OFF_SCORE;

    for (int p = 0; p < Pn; ++p) {
        long long h, o;
        if (is64) {
            const long long* p64 = (const long long*)pairs_raw + (size_t)b * Pn * 2;
            h = p64[2 * p];
            o = p64[2 * p + 1];
        } else {
            const int* p32 = pw + (size_t)b * Pn * 2;
            h = p32[2 * p];
            o = p32[2 * p + 1];
        }
        if (h == o) o = Qn;
        if (lane < An) {
            float x = act_b[(size_t)p * An + lane];
            float v = 1.f / (1.f + expf(-x));
            size_t idx = (((size_t)b * An + (size_t)lane) * Qn + (size_t)h) * (Qn + 1) + (size_t)o;
            score_base[idx] = v;
        }
    }
}

// ---------------------------------------------------------------------------
// Launch
// ---------------------------------------------------------------------------
extern "C" void kernel_launch(void* const* d_in, const int* in_sizes, int n_in,
                              void* d_out, int out_size) {
    const float* pred_logits    = (const float*)d_in[0];  // (B,Q,C)
    const float* pred_boxes     = (const float*)d_in[1];  // (B,Q,4)
    const float* pred_actions   = (const float*)d_in[2];  // (B,P,A)
    const void*  pred_rel_pairs = d_in[3];                // (B,P,2) int32 or int64
    const float* target_sizes   = (const float*)d_in[4];  // (B,2)

    float* out = (float*)d_out;

    // Zero the entire output (score tensor is 99.6% of it and must be zeroed;
    // the small regions are fully overwritten below). Memset node hits peak BW.
    size_t total = OFF_OMASK + LEN_OMASK;  // 83,875,232 floats
    cudaMemsetAsync(d_out, 0, total * sizeof(float), 0);

    // Per-row stats: 9600 warps, 8 warps/block
    int warps = Bn * Qn;
    int threads = 256;
    int blocks = (warps * 32 + threads - 1) / threads;
    postproc_rows_kernel<<<blocks, threads>>>(pred_logits, pred_boxes,
                                              target_sizes, out);

    // Scatter: one 32-thread block per batch (serialized over p for
    // deterministic duplicate resolution)
    scatter_actions_kernel<<<Bn, 32>>>(pred_actions, pred_rel_pairs, out);
}

// round 2
// speedup vs baseline: 2.4686x; 2.4686x over previous
#include <cuda_runtime.h>
#include <cstdint>
#include <math.h>

#define Bn 32
#define Qn 300
#define Cn 81
#define Pn 300
#define An 29

// Output layout (flattened float32, concatenated in reference return order)
#define LEN_SCORES ((size_t)Bn * Qn)                        // 9600
#define LEN_LABELS ((size_t)Bn * Qn)                        // 9600
#define LEN_BOXES  ((size_t)Bn * Qn * 4)                    // 38400
#define LEN_SCORE  ((size_t)Bn * An * Qn * (Qn + 1))        // 83,798,400
#define LEN_HMASK  ((size_t)Bn * Qn)                        // 9600
#define LEN_OMASK  ((size_t)Bn * (Qn + 1))                  // 9632

#define OFF_SCORES ((size_t)0)
#define OFF_LABELS (OFF_SCORES + LEN_SCORES)
#define OFF_BOXES  (OFF_LABELS + LEN_LABELS)
#define OFF_SCORE  (OFF_BOXES  + LEN_BOXES)
#define OFF_HMASK  (OFF_SCORE  + LEN_SCORE)
#define OFF_OMASK  (OFF_HMASK  + LEN_HMASK)

// ---------------------------------------------------------------------------
// Kernel 1: per-(b,q) softmax stats + boxes + masks. One warp per row.
// ---------------------------------------------------------------------------
__global__ void postproc_rows_kernel(const float* __restrict__ logits,
                                     const float* __restrict__ boxes_in,
                                     const float* __restrict__ tsizes,
                                     float* __restrict__ out) {
    int gwarp = (blockIdx.x * blockDim.x + threadIdx.x) >> 5;
    int lane  = threadIdx.x & 31;
    if (gwarp >= Bn * Qn) return;
    int b = gwarp / Qn;
    int q = gwarp % Qn;

    const float* row = logits + (size_t)gwarp * Cn;

    // Load up to 3 classes per lane (81 = 32 + 32 + 17)
    float v0 = (lane      < Cn) ? row[lane]      : -INFINITY;
    float v1 = (lane + 32 < Cn) ? row[lane + 32] : -INFINITY;
    float v2 = (lane + 64 < Cn) ? row[lane + 64] : -INFINITY;

    // Max over all C classes (for softmax stability)
    float m_all = fmaxf(v0, fmaxf(v1, v2));
    #pragma unroll
    for (int off = 16; off > 0; off >>= 1)
        m_all = fmaxf(m_all, __shfl_xor_sync(0xffffffffu, m_all, off));

    // Argmax over first C-1 = 80 classes (first-index-wins on ties)
    float bv = -INFINITY; int bi = 0;
    if (lane < Cn - 1)            { bv = v0; bi = lane; }
    if (lane + 32 < Cn - 1 && v1 > bv) { bv = v1; bi = lane + 32; }
    if (lane + 64 < Cn - 1 && v2 > bv) { bv = v2; bi = lane + 64; }
    #pragma unroll
    for (int off = 16; off > 0; off >>= 1) {
        float ov = __shfl_xor_sync(0xffffffffu, bv, off);
        int   oi = __shfl_xor_sync(0xffffffffu, bi, off);
        if (ov > bv || (ov == bv && oi < bi)) { bv = ov; bi = oi; }
    }

    // Sum of exp
    float s = 0.f;
    if (lane      < Cn) s += expf(v0 - m_all);
    if (lane + 32 < Cn) s += expf(v1 - m_all);
    if (lane + 64 < Cn) s += expf(v2 - m_all);
    #pragma unroll
    for (int off = 16; off > 0; off >>= 1)
        s += __shfl_xor_sync(0xffffffffu, s, off);

    float score = expf(bv - m_all) / s;

    if (lane == 0) {
        out[OFF_SCORES + gwarp] = score;
        out[OFF_LABELS + gwarp] = (float)bi;
        out[OFF_HMASK  + gwarp] = (bi == 1 && score > 0.f) ? 1.f : 0.f;
        out[OFF_OMASK + (size_t)b * (Qn + 1) + q] = (score > 0.f) ? 1.f : 0.f;
        if (q == 0)
            out[OFF_OMASK + (size_t)b * (Qn + 1) + Qn] = 1.f;
    }

    // Boxes: cxcywh -> xyxy, scaled by [w,h,w,h]
    if (lane < 4) {
        float cxy = boxes_in[(size_t)gwarp * 4 + (lane & 1)];        // cx or cy
        float wh  = boxes_in[(size_t)gwarp * 4 + 2 + (lane & 1)];    // w or h
        float v   = cxy + ((lane < 2) ? -0.5f : 0.5f) * wh;
        float img_h = tsizes[b * 2 + 0];
        float img_w = tsizes[b * 2 + 1];
        float scale = (lane & 1) ? img_h : img_w;
        out[OFF_BOXES + (size_t)gwarp * 4 + lane] = v * scale;
    }
}

// ---------------------------------------------------------------------------
// Kernel 2 (parallel): scatter sigmoid(pred_actions) into score[b, a, h, o].
// One 256-thread block per batch. Duplicate (h,o) pairs are resolved
// last-wins WITHOUT serialization: each p checks (in smem) whether a later
// p' shares its key; only the last occurrence writes. Deterministic.
// Runtime-detects whether pairs are int32 or int64 (JAX x64 ambiguity).
// ---------------------------------------------------------------------------
__global__ void scatter_actions_par_kernel(const float* __restrict__ actions,
                                           const void*  __restrict__ pairs_raw,
                                           float* __restrict__ out) {
    __shared__ int keys[Pn];
    __shared__ unsigned char win[Pn];
    __shared__ int is64_s;

    int b = blockIdx.x;
    int tid = threadIdx.x;

    // dtype detection: if data is int64 (values in [0,Q), nonneg), every odd
    // 32-bit word is the zero high-half. Sample 32 odd words from batch 0.
    if (tid < 32) {
        const int* pw = (const int*)pairs_raw;
        int nonzero = (pw[2 * tid + 1] != 0) ? 1 : 0;
        unsigned mask = __ballot_sync(0xffffffffu, nonzero);
        if (tid == 0) is64_s = (mask == 0u) ? 1 : 0;
    }
    __syncthreads();
    bool is64 = (is64_s != 0);

    // Load keys for this batch into smem (with h==o -> o=Q remap)
    for (int p = tid; p < Pn; p += blockDim.x) {
        int h, o;
        if (is64) {
            const long long* p64 = (const long long*)pairs_raw + (size_t)b * Pn * 2;
            h = (int)p64[2 * p];
            o = (int)p64[2 * p + 1];
        } else {
            const int* p32 = (const int*)pairs_raw + (size_t)b * Pn * 2;
            h = p32[2 * p];
            o = p32[2 * p + 1];
        }
        if (h == o) o = Qn;
        keys[p] = h * (Qn + 1) + o;   // < 300*301+300, fits easily in int32
    }
    __syncthreads();

    // Winner = last occurrence of each key
    for (int p = tid; p < Pn; p += blockDim.x) {
        int k = keys[p];
        unsigned char w = 1;
        for (int p2 = p + 1; p2 < Pn; ++p2) {
            if (keys[p2] == k) { w = 0; break; }
        }
        win[p] = w;
    }
    __syncthreads();

    // Parallel scattered writes: (p, a) pairs, winners only
    const float* act_b = actions + (size_t)b * Pn * An;
    float* sb = out + OFF_SCORE + (size_t)b * An * Qn * (Qn + 1);
    for (int idx = tid; idx < Pn * An; idx += blockDim.x) {
        int p = idx / An;
        int a = idx - p * An;
        if (!win[p]) continue;
        float x = act_b[(size_t)p * An + a];
        float v = 1.f / (1.f + expf(-x));
        sb[(size_t)a * Qn * (Qn + 1) + keys[p]] = v;
    }
}

// ---------------------------------------------------------------------------
// Launch
// ---------------------------------------------------------------------------
extern "C" void kernel_launch(void* const* d_in, const int* in_sizes, int n_in,
                              void* d_out, int out_size) {
    const float* pred_logits    = (const float*)d_in[0];  // (B,Q,C)
    const float* pred_boxes     = (const float*)d_in[1];  // (B,Q,4)
    const float* pred_actions   = (const float*)d_in[2];  // (B,P,A)
    const void*  pred_rel_pairs = d_in[3];                // (B,P,2) int32 or int64
    const float* target_sizes   = (const float*)d_in[4];  // (B,2)

    float* out = (float*)d_out;

    // Zero the entire output (score tensor is 99.6% of it and must be zeroed;
    // the small regions are fully overwritten below). Memset node hits peak BW.
    size_t total = OFF_OMASK + LEN_OMASK;  // 83,875,232 floats
    cudaMemsetAsync(d_out, 0, total * sizeof(float), 0);

    // Per-row stats: 9600 warps, 8 warps/block
    int warps = Bn * Qn;
    int threads = 256;
    int blocks = (warps * 32 + threads - 1) / threads;
    postproc_rows_kernel<<<blocks, threads>>>(pred_logits, pred_boxes,
                                              target_sizes, out);

    // Fully parallel scatter with deterministic last-wins duplicate handling
    scatter_actions_par_kernel<<<Bn, 256>>>(pred_actions, pred_rel_pairs, out);
}

// round 3
// speedup vs baseline: 2.7300x; 1.1059x over previous
#include <cuda_runtime.h>
#include <cstdint>
#include <math.h>

#define Bn 32
#define Qn 300
#define Cn 81
#define Pn 300
#define An 29

#define LEN_SCORES ((size_t)Bn * Qn)                        // 9600
#define LEN_LABELS ((size_t)Bn * Qn)                        // 9600
#define LEN_BOXES  ((size_t)Bn * Qn * 4)                    // 38400
#define LEN_SCORE  ((size_t)Bn * An * Qn * (Qn + 1))        // 83,798,400
#define LEN_HMASK  ((size_t)Bn * Qn)                        // 9600
#define LEN_OMASK  ((size_t)Bn * (Qn + 1))                  // 9632

#define OFF_SCORES ((size_t)0)
#define OFF_LABELS (OFF_SCORES + LEN_SCORES)
#define OFF_BOXES  (OFF_LABELS + LEN_LABELS)
#define OFF_SCORE  (OFF_BOXES  + LEN_BOXES)                 // 57600 (16B-aligned*4)
#define OFF_HMASK  (OFF_SCORE  + LEN_SCORE)
#define OFF_OMASK  (OFF_HMASK  + LEN_HMASK)

#define PLANE_ELEMS (Qn * (Qn + 1))        // 90300 floats per (b,a) plane
#define PLANE_VEC4  (PLANE_ELEMS / 4)      // 22575 float4 stores (exact)
#define SCORE_BLOCKS (Bn * An)             // 928
#define ROW_BLOCKS   ((Bn * Qn) / 8)       // 1200 (8 warps/block)

// ---------------------------------------------------------------------------
// Fused kernel.
// Blocks [0, SCORE_BLOCKS): one (b,a) score plane each — zero-stream with
//   float4, then overwrite scattered winner positions (last-wins, resolved
//   via smem O(P^2) scan). Intra-block __syncthreads orders zero vs scatter.
// Blocks [SCORE_BLOCKS, SCORE_BLOCKS+ROW_BLOCKS): per-(b,q) softmax stats,
//   boxes, masks — one warp per row, 8 rows per block.
// Every output element is written exactly once -> no memset needed.
// ---------------------------------------------------------------------------
__global__ void __launch_bounds__(256) fused_postproc_kernel(
        const float* __restrict__ logits,
        const float* __restrict__ boxes_in,
        const float* __restrict__ actions,
        const void*  __restrict__ pairs_raw,
        const float* __restrict__ tsizes,
        float* __restrict__ out) {

    int blk = blockIdx.x;
    int tid = threadIdx.x;

    if (blk < SCORE_BLOCKS) {
        // ---------------- score plane block ----------------
        int b = blk / An;
        int a = blk - b * An;

        __shared__ int   keys[Pn];
        __shared__ float vals[Pn];
        __shared__ unsigned char win[Pn];
        __shared__ int is64_s;

        // dtype detection (int32 vs int64 pairs): if int64 with values in
        // [0,Q), every odd 32-bit word is the zero high-half.
        if (tid < 32) {
            const int* pw = (const int*)pairs_raw;
            int nonzero = (pw[2 * tid + 1] != 0) ? 1 : 0;
            unsigned m = __ballot_sync(0xffffffffu, nonzero);
            if (tid == 0) is64_s = (m == 0u) ? 1 : 0;
        }
        __syncthreads();
        bool is64 = (is64_s != 0);

        // Load keys (h,o)->h*(Q+1)+o with h==o -> o=Q remap, plus this a's
        // sigmoid values.
        const float* act_b = actions + (size_t)b * Pn * An;
        for (int p = tid; p < Pn; p += blockDim.x) {
            int h, o;
            if (is64) {
                const long long* p64 = (const long long*)pairs_raw + (size_t)b * Pn * 2;
                h = (int)p64[2 * p];
                o = (int)p64[2 * p + 1];
            } else {
                const int* p32 = (const int*)pairs_raw + (size_t)b * Pn * 2;
                h = p32[2 * p];
                o = p32[2 * p + 1];
            }
            if (h == o) o = Qn;
            keys[p] = h * (Qn + 1) + o;
            float x = act_b[(size_t)p * An + a];
            vals[p] = 1.f / (1.f + expf(-x));
        }
        __syncthreads();

        // Winner = last occurrence of each key
        for (int p = tid; p < Pn; p += blockDim.x) {
            int k = keys[p];
            unsigned char w = 1;
            for (int p2 = p + 1; p2 < Pn; ++p2)
                if (keys[p2] == k) { w = 0; break; }
            win[p] = w;
        }

        // Zero-stream the plane with float4 (no dependency on smem phase)
        float4* plane4 = (float4*)(out + OFF_SCORE + (size_t)blk * PLANE_ELEMS);
        float4 z = make_float4(0.f, 0.f, 0.f, 0.f);
        for (int i = tid; i < PLANE_VEC4; i += blockDim.x)
            plane4[i] = z;

        __syncthreads();

        // Scatter winners over the zeros (same block -> ordered)
        float* plane = out + OFF_SCORE + (size_t)blk * PLANE_ELEMS;
        for (int p = tid; p < Pn; p += blockDim.x)
            if (win[p]) plane[keys[p]] = vals[p];

    } else {
        // ---------------- rows block: 8 warps, one (b,q) row each --------
        int r = blk - SCORE_BLOCKS;
        int gwarp = r * 8 + (tid >> 5);
        int lane  = tid & 31;
        if (gwarp >= Bn * Qn) return;
        int b = gwarp / Qn;
        int q = gwarp - b * Qn;

        const float* row = logits + (size_t)gwarp * Cn;

        float v0 = (lane      < Cn) ? row[lane]      : -INFINITY;
        float v1 = (lane + 32 < Cn) ? row[lane + 32] : -INFINITY;
        float v2 = (lane + 64 < Cn) ? row[lane + 64] : -INFINITY;

        // Max over all C classes
        float m_all = fmaxf(v0, fmaxf(v1, v2));
        #pragma unroll
        for (int off = 16; off > 0; off >>= 1)
            m_all = fmaxf(m_all, __shfl_xor_sync(0xffffffffu, m_all, off));

        // Argmax over first C-1 classes (first-index-wins on ties)
        float bv = -INFINITY; int bi = 0;
        if (lane < Cn - 1)                 { bv = v0; bi = lane; }
        if (lane + 32 < Cn - 1 && v1 > bv) { bv = v1; bi = lane + 32; }
        if (lane + 64 < Cn - 1 && v2 > bv) { bv = v2; bi = lane + 64; }
        #pragma unroll
        for (int off = 16; off > 0; off >>= 1) {
            float ov = __shfl_xor_sync(0xffffffffu, bv, off);
            int   oi = __shfl_xor_sync(0xffffffffu, bi, off);
            if (ov > bv || (ov == bv && oi < bi)) { bv = ov; bi = oi; }
        }

        // Sum of exp
        float s = 0.f;
        if (lane      < Cn) s += expf(v0 - m_all);
        if (lane + 32 < Cn) s += expf(v1 - m_all);
        if (lane + 64 < Cn) s += expf(v2 - m_all);
        #pragma unroll
        for (int off = 16; off > 0; off >>= 1)
            s += __shfl_xor_sync(0xffffffffu, s, off);

        float score = expf(bv - m_all) / s;

        if (lane == 0) {
            out[OFF_SCORES + gwarp] = score;
            out[OFF_LABELS + gwarp] = (float)bi;
            out[OFF_HMASK  + gwarp] = (bi == 1 && score > 0.f) ? 1.f : 0.f;
            out[OFF_OMASK + (size_t)b * (Qn + 1) + q] = (score > 0.f) ? 1.f : 0.f;
            if (q == 0)
                out[OFF_OMASK + (size_t)b * (Qn + 1) + Qn] = 1.f;
        }

        // Boxes: cxcywh -> xyxy scaled by [w,h,w,h]
        if (lane < 4) {
            float cxy = boxes_in[(size_t)gwarp * 4 + (lane & 1)];
            float wh  = boxes_in[(size_t)gwarp * 4 + 2 + (lane & 1)];
            float v   = cxy + ((lane < 2) ? -0.5f : 0.5f) * wh;
            float img_h = tsizes[b * 2 + 0];
            float img_w = tsizes[b * 2 + 1];
            float scale = (lane & 1) ? img_h : img_w;
            out[OFF_BOXES + (size_t)gwarp * 4 + lane] = v * scale;
        }
    }
}

extern "C" void kernel_launch(void* const* d_in, const int* in_sizes, int n_in,
                              void* d_out, int out_size) {
    const float* pred_logits    = (const float*)d_in[0];  // (B,Q,C)
    const float* pred_boxes     = (const float*)d_in[1];  // (B,Q,4)
    const float* pred_actions   = (const float*)d_in[2];  // (B,P,A)
    const void*  pred_rel_pairs = d_in[3];                // (B,P,2) int32/int64
    const float* target_sizes   = (const float*)d_in[4];  // (B,2)

    float* out = (float*)d_out;

    int grid = SCORE_BLOCKS + ROW_BLOCKS;  // 928 + 1200 = 2128
    fused_postproc_kernel<<<grid, 256>>>(pred_logits, pred_boxes, pred_actions,
                                         pred_rel_pairs, target_sizes, out);
}

// round 4
// speedup vs baseline: 2.9325x; 1.0741x over previous
#include <cuda_runtime.h>
#include <cstdint>
#include <math.h>

#define Bn 32
#define Qn 300
#define Cn 81
#define Pn 300
#define An 29

#define LEN_SCORES ((size_t)Bn * Qn)                        // 9600
#define LEN_LABELS ((size_t)Bn * Qn)                        // 9600
#define LEN_BOXES  ((size_t)Bn * Qn * 4)                    // 38400
#define LEN_SCORE  ((size_t)Bn * An * Qn * (Qn + 1))        // 83,798,400
#define LEN_HMASK  ((size_t)Bn * Qn)                        // 9600
#define LEN_OMASK  ((size_t)Bn * (Qn + 1))                  // 9632

#define OFF_SCORES ((size_t)0)
#define OFF_LABELS (OFF_SCORES + LEN_SCORES)
#define OFF_BOXES  (OFF_LABELS + LEN_LABELS)
#define OFF_SCORE  (OFF_BOXES  + LEN_BOXES)
#define OFF_HMASK  (OFF_SCORE  + LEN_SCORE)
#define OFF_OMASK  (OFF_HMASK  + LEN_HMASK)

#define PLANE_ELEMS (Qn * (Qn + 1))        // 90300
#define SCORE_BLOCKS (Bn * An)             // 928
#define ROW_BLOCKS   ((Bn * Qn) / 8)       // 1200

// ---------------------------------------------------------------------------
// Small fused kernel (runs AFTER the memset node):
// Blocks [0, SCORE_BLOCKS): one (b,a) plane each — scatter sigmoid values at
//   winner positions (last-wins resolved via smem O(P^2) scan). Zeros already
//   laid down by the memset node; stream order guarantees visibility.
// Blocks [SCORE_BLOCKS, +ROW_BLOCKS): per-(b,q) softmax/boxes/masks,
//   one warp per row, 8 rows per block.
// ---------------------------------------------------------------------------
__global__ void __launch_bounds__(256) scatter_rows_kernel(
        const float* __restrict__ logits,
        const float* __restrict__ boxes_in,
        const float* __restrict__ actions,
        const void*  __restrict__ pairs_raw,
        const float* __restrict__ tsizes,
        float* __restrict__ out) {

    int blk = blockIdx.x;
    int tid = threadIdx.x;

    if (blk < SCORE_BLOCKS) {
        // ---------------- scatter block for plane (b,a) ----------------
        int b = blk / An;
        int a = blk - b * An;

        __shared__ int   keys[Pn];
        __shared__ float vals[Pn];
        __shared__ int is64_s;

        // dtype detection (int32 vs int64 pairs): int64 values in [0,Q)
        // have all-zero odd 32-bit words.
        if (tid < 32) {
            const int* pw = (const int*)pairs_raw;
            int nonzero = (pw[2 * tid + 1] != 0) ? 1 : 0;
            unsigned m = __ballot_sync(0xffffffffu, nonzero);
            if (tid == 0) is64_s = (m == 0u) ? 1 : 0;
        }
        __syncthreads();
        bool is64 = (is64_s != 0);

        const float* act_b = actions + (size_t)b * Pn * An;
        for (int p = tid; p < Pn; p += blockDim.x) {
            int h, o;
            if (is64) {
                const long long* p64 = (const long long*)pairs_raw + (size_t)b * Pn * 2;
                h = (int)p64[2 * p];
                o = (int)p64[2 * p + 1];
            } else {
                const int* p32 = (const int*)pairs_raw + (size_t)b * Pn * 2;
                h = p32[2 * p];
                o = p32[2 * p + 1];
            }
            if (h == o) o = Qn;
            keys[p] = h * (Qn + 1) + o;
            float x = act_b[(size_t)p * An + a];
            vals[p] = 1.f / (1.f + expf(-x));
        }
        __syncthreads();

        // Winner = last occurrence of each key; winners write directly.
        float* plane = out + OFF_SCORE + (size_t)blk * PLANE_ELEMS;
        for (int p = tid; p < Pn; p += blockDim.x) {
            int k = keys[p];
            bool w = true;
            for (int p2 = p + 1; p2 < Pn; ++p2)
                if (keys[p2] == k) { w = false; break; }
            if (w) plane[k] = vals[p];
        }

    } else {
        // ---------------- rows block: 8 warps, one (b,q) row each --------
        int r = blk - SCORE_BLOCKS;
        int gwarp = r * 8 + (tid >> 5);
        int lane  = tid & 31;
        if (gwarp >= Bn * Qn) return;
        int b = gwarp / Qn;
        int q = gwarp - b * Qn;

        const float* row = logits + (size_t)gwarp * Cn;

        float v0 = (lane      < Cn) ? row[lane]      : -INFINITY;
        float v1 = (lane + 32 < Cn) ? row[lane + 32] : -INFINITY;
        float v2 = (lane + 64 < Cn) ? row[lane + 64] : -INFINITY;

        // Max over all C classes
        float m_all = fmaxf(v0, fmaxf(v1, v2));
        #pragma unroll
        for (int off = 16; off > 0; off >>= 1)
            m_all = fmaxf(m_all, __shfl_xor_sync(0xffffffffu, m_all, off));

        // Argmax over first C-1 classes (first-index-wins on ties)
        float bv = -INFINITY; int bi = 0;
        if (lane < Cn - 1)                 { bv = v0; bi = lane; }
        if (lane + 32 < Cn - 1 && v1 > bv) { bv = v1; bi = lane + 32; }
        if (lane + 64 < Cn - 1 && v2 > bv) { bv = v2; bi = lane + 64; }
        #pragma unroll
        for (int off = 16; off > 0; off >>= 1) {
            float ov = __shfl_xor_sync(0xffffffffu, bv, off);
            int   oi = __shfl_xor_sync(0xffffffffu, bi, off);
            if (ov > bv || (ov == bv && oi < bi)) { bv = ov; bi = oi; }
        }

        // Sum of exp
        float s = 0.f;
        if (lane      < Cn) s += expf(v0 - m_all);
        if (lane + 32 < Cn) s += expf(v1 - m_all);
        if (lane + 64 < Cn) s += expf(v2 - m_all);
        #pragma unroll
        for (int off = 16; off > 0; off >>= 1)
            s += __shfl_xor_sync(0xffffffffu, s, off);

        float score = expf(bv - m_all) / s;

        if (lane == 0) {
            out[OFF_SCORES + gwarp] = score;
            out[OFF_LABELS + gwarp] = (float)bi;
            out[OFF_HMASK  + gwarp] = (bi == 1 && score > 0.f) ? 1.f : 0.f;
            out[OFF_OMASK + (size_t)b * (Qn + 1) + q] = (score > 0.f) ? 1.f : 0.f;
            if (q == 0)
                out[OFF_OMASK + (size_t)b * (Qn + 1) + Qn] = 1.f;
        }

        // Boxes: cxcywh -> xyxy scaled by [w,h,w,h]
        if (lane < 4) {
            float cxy = boxes_in[(size_t)gwarp * 4 + (lane & 1)];
            float wh  = boxes_in[(size_t)gwarp * 4 + 2 + (lane & 1)];
            float v   = cxy + ((lane < 2) ? -0.5f : 0.5f) * wh;
            float img_h = tsizes[b * 2 + 0];
            float img_w = tsizes[b * 2 + 1];
            float scale = (lane & 1) ? img_h : img_w;
            out[OFF_BOXES + (size_t)gwarp * 4 + lane] = v * scale;
        }
    }
}

extern "C" void kernel_launch(void* const* d_in, const int* in_sizes, int n_in,
                              void* d_out, int out_size) {
    const float* pred_logits    = (const float*)d_in[0];  // (B,Q,C)
    const float* pred_boxes     = (const float*)d_in[1];  // (B,Q,4)
    const float* pred_actions   = (const float*)d_in[2];  // (B,P,A)
    const void*  pred_rel_pairs = d_in[3];                // (B,P,2) int32/int64
    const float* target_sizes   = (const float*)d_in[4];  // (B,2)

    float* out = (float*)d_out;

    // Zero only the big score region with the driver memset (proven ~6.4 TB/s).
    // All other output regions are fully written by the kernel below.
    cudaMemsetAsync(out + OFF_SCORE, 0, LEN_SCORE * sizeof(float), 0);

    // Small fused kernel: scattered winner writes + per-row stats.
    int grid = SCORE_BLOCKS + ROW_BLOCKS;  // 2128
    scatter_rows_kernel<<<grid, 256>>>(pred_logits, pred_boxes, pred_actions,
                                       pred_rel_pairs, target_sizes, out);
}